// round 1
// baseline (speedup 1.0000x reference)
#include <cuda_runtime.h>

#define BB 2
#define NQv 1024
#define NKv 1024
#define DD 512
#define HH 32

// Scratch for projected keys/queries (no cudaMalloc allowed)
__device__ float g_hk[BB * NKv * HH];   // keys @ W1[:D] + b1
__device__ float g_hq[BB * NQv * HH];   // queries @ W1[D:]

__device__ __forceinline__ float tanh_fast(float x) {
    float y;
    asm("tanh.approx.f32 %0, %1;" : "=f"(y) : "f"(x));
    return y;
}

// ---------------------------------------------------------------------------
// Projection: rows = B*1024 per tensor. Each block handles 64 rows of one
// tensor (blockIdx.y: 0=keys->g_hk(+b1), 1=queries->g_hq).
// W1 chunk (256 x 32 = 32KB) staged in smem; keys rows read as uniform-address
// float4 LDG (each element touched exactly once).
// ---------------------------------------------------------------------------
__global__ __launch_bounds__(256) void proj_kernel(
    const float* __restrict__ keys, const float* __restrict__ queries,
    const float* __restrict__ W1, const float* __restrict__ b1)
{
    __shared__ float w1s[256][32];   // [d_chunk][h]
    const int z   = blockIdx.y;
    const int tid = threadIdx.x;
    const int h   = tid & 31;
    const int warp = tid >> 5;
    const int rowbase = blockIdx.x * 64 + warp * 8;   // global row 0..2047
    const float* __restrict__ src = z ? queries : keys;
    float* __restrict__ dst = z ? g_hq : g_hk;
    const int w1row0 = z * DD;    // W1 row offset for this tensor

    float acc[8];
    #pragma unroll
    for (int i = 0; i < 8; ++i) acc[i] = 0.f;

    #pragma unroll
    for (int c = 0; c < 2; ++c) {
        // Cooperative load of W1 chunk: 256x32 floats = 2048 float4
        const float4* __restrict__ w1g =
            (const float4*)(W1 + (size_t)(w1row0 + c * 256) * HH);
        float4* w1sv = (float4*)&w1s[0][0];
        #pragma unroll
        for (int i = 0; i < 8; ++i)
            w1sv[tid + i * 256] = __ldg(&w1g[tid + i * 256]);
        __syncthreads();

        const float4* __restrict__ srow0 =
            (const float4*)(src + (size_t)rowbase * DD + c * 256);

        #pragma unroll 4
        for (int d4 = 0; d4 < 64; ++d4) {
            const float w0 = w1s[d4 * 4 + 0][h];
            const float w1v = w1s[d4 * 4 + 1][h];
            const float w2v = w1s[d4 * 4 + 2][h];
            const float w3v = w1s[d4 * 4 + 3][h];
            #pragma unroll
            for (int i = 0; i < 8; ++i) {
                const float4 kv = __ldg(srow0 + (size_t)i * (DD / 4) + d4);
                acc[i] = fmaf(kv.x, w0,  acc[i]);
                acc[i] = fmaf(kv.y, w1v, acc[i]);
                acc[i] = fmaf(kv.z, w2v, acc[i]);
                acc[i] = fmaf(kv.w, w3v, acc[i]);
            }
        }
        __syncthreads();
    }

    const float bias = z ? 0.f : __ldg(&b1[h]);
    #pragma unroll
    for (int i = 0; i < 8; ++i)
        dst[(size_t)(rowbase + i) * HH + h] = acc[i] + bias;
}

// ---------------------------------------------------------------------------
// Scoring: 32x32 output tile per 256-thread block; each thread owns a 2x2
// register block. MUFU(tanh)-bound by design. smem padded to stride 33 for
// conflict-free strided reads.
// ---------------------------------------------------------------------------
__global__ __launch_bounds__(256) void score_kernel(
    const float* __restrict__ W2, const float* __restrict__ b2,
    float* __restrict__ out)
{
    __shared__ float hqs[32][33];
    __shared__ float hks[32][33];
    __shared__ float w2s[32];

    const int b  = blockIdx.z;
    const int q0 = blockIdx.y * 32;
    const int k0 = blockIdx.x * 32;
    const int tid = threadIdx.x;

    {
        const float* __restrict__ hq_g = g_hq + (size_t)(b * NQv + q0) * HH;
        const float* __restrict__ hk_g = g_hk + (size_t)(b * NKv + k0) * HH;
        int i = tid;
        #pragma unroll
        for (int it = 0; it < 4; ++it) {
            const int r = i >> 5, hh = i & 31;
            hqs[r][hh] = hq_g[i];
            hks[r][hh] = hk_g[i];
            i += 256;
        }
        if (tid < 32) w2s[tid] = W2[tid];
    }
    __syncthreads();

    const int kk = (tid & 15) * 2;
    const int qq = (tid >> 4) * 2;

    float a00 = 0.f, a01 = 0.f, a10 = 0.f, a11 = 0.f;
    #pragma unroll
    for (int h = 0; h < 32; ++h) {
        const float w   = w2s[h];
        const float aq0 = hqs[qq][h];
        const float aq1 = hqs[qq + 1][h];
        const float bk0 = hks[kk][h];
        const float bk1 = hks[kk + 1][h];
        a00 = fmaf(w, tanh_fast(aq0 + bk0), a00);
        a01 = fmaf(w, tanh_fast(aq0 + bk1), a01);
        a10 = fmaf(w, tanh_fast(aq1 + bk0), a10);
        a11 = fmaf(w, tanh_fast(aq1 + bk1), a11);
    }

    const float bias = __ldg(b2);
    float* __restrict__ o = out + (size_t)(b * NQv + q0 + qq) * NKv + k0 + kk;
    *(float2*)o          = make_float2(a00 + bias, a01 + bias);
    *(float2*)(o + NKv)  = make_float2(a10 + bias, a11 + bias);
}

extern "C" void kernel_launch(void* const* d_in, const int* in_sizes, int n_in,
                              void* d_out, int out_size)
{
    const float* keys    = (const float*)d_in[0];
    const float* queries = (const float*)d_in[1];
    const float* W1      = (const float*)d_in[2];
    const float* b1      = (const float*)d_in[3];
    const float* W2      = (const float*)d_in[4];
    const float* b2      = (const float*)d_in[5];
    float* out = (float*)d_out;

    // Projection: (B*1024 rows)/64 per block = 32 blocks, y = tensor select
    proj_kernel<<<dim3(32, 2, 1), 256>>>(keys, queries, W1, b1);
    // Scoring: (NK/32, NQ/32, B)
    score_kernel<<<dim3(NKv / 32, NQv / 32, BB), 256>>>(W2, b2, out);
}

// round 2
// speedup vs baseline: 1.4522x; 1.4522x over previous
#include <cuda_runtime.h>

#define BB 2
#define NQv 1024
#define NKv 1024
#define DD 512
#define HH 32

// Scratch for projected keys/queries (no cudaMalloc allowed)
__device__ float g_hk[BB * NKv * HH];   // keys @ W1[:D] + b1
__device__ float g_hq[BB * NQv * HH];   // queries @ W1[D:]

__device__ __forceinline__ float tanh_fast(float x) {
    float y;
    asm("tanh.approx.f32 %0, %1;" : "=f"(y) : "f"(x));
    return y;
}

// ---------------------------------------------------------------------------
// Projection v2: C[2048,32] = A[2048,512] @ W[512,32] per tensor.
// 128 blocks (64 x 2 tensors), 256 threads. Each warp owns 4 rows (all 32 h
// across lanes); each thread accumulates 4 rows for its h. W1 staged in smem
// as 256x32 chunks. 4 independent uniform LDG.128 per d4 step -> MLP >= 8
// with unroll 2. FMA-bound by design (~16 FMA per 4 LDS + 4 LDG).
// ---------------------------------------------------------------------------
__global__ __launch_bounds__(256) void proj_kernel(
    const float* __restrict__ keys, const float* __restrict__ queries,
    const float* __restrict__ W1, const float* __restrict__ b1)
{
    __shared__ float w1s[256][32];   // [d_chunk][h]
    const int z    = blockIdx.y;
    const int tid  = threadIdx.x;
    const int h    = tid & 31;
    const int warp = tid >> 5;
    const int rowbase = blockIdx.x * 32 + warp * 4;   // 32 rows per block
    const float* __restrict__ src = z ? queries : keys;
    float* __restrict__ dst = z ? g_hq : g_hk;
    const int w1row0 = z * DD;

    float acc0 = 0.f, acc1 = 0.f, acc2 = 0.f, acc3 = 0.f;

    #pragma unroll
    for (int c = 0; c < 2; ++c) {
        // Cooperative load of W1 chunk: 256x32 floats = 2048 float4
        const float4* __restrict__ w1g =
            (const float4*)(W1 + (size_t)(w1row0 + c * 256) * HH);
        float4* w1sv = (float4*)&w1s[0][0];
        #pragma unroll
        for (int i = 0; i < 8; ++i)
            w1sv[tid + i * 256] = __ldg(&w1g[tid + i * 256]);
        __syncthreads();

        const float4* __restrict__ srow =
            (const float4*)(src + (size_t)rowbase * DD + c * 256);

        #pragma unroll 4
        for (int d4 = 0; d4 < 64; ++d4) {
            // 4 independent row loads (uniform across the warp -> broadcast)
            const float4 k0 = __ldg(srow + 0 * (DD / 4) + d4);
            const float4 k1 = __ldg(srow + 1 * (DD / 4) + d4);
            const float4 k2 = __ldg(srow + 2 * (DD / 4) + d4);
            const float4 k3 = __ldg(srow + 3 * (DD / 4) + d4);
            const float w0 = w1s[d4 * 4 + 0][h];
            const float w1v = w1s[d4 * 4 + 1][h];
            const float w2v = w1s[d4 * 4 + 2][h];
            const float w3v = w1s[d4 * 4 + 3][h];
            acc0 = fmaf(k0.x, w0, acc0); acc0 = fmaf(k0.y, w1v, acc0);
            acc0 = fmaf(k0.z, w2v, acc0); acc0 = fmaf(k0.w, w3v, acc0);
            acc1 = fmaf(k1.x, w0, acc1); acc1 = fmaf(k1.y, w1v, acc1);
            acc1 = fmaf(k1.z, w2v, acc1); acc1 = fmaf(k1.w, w3v, acc1);
            acc2 = fmaf(k2.x, w0, acc2); acc2 = fmaf(k2.y, w1v, acc2);
            acc2 = fmaf(k2.z, w2v, acc2); acc2 = fmaf(k2.w, w3v, acc2);
            acc3 = fmaf(k3.x, w0, acc3); acc3 = fmaf(k3.y, w1v, acc3);
            acc3 = fmaf(k3.z, w2v, acc3); acc3 = fmaf(k3.w, w3v, acc3);
        }
        __syncthreads();
    }

    const float bias = z ? 0.f : __ldg(&b1[h]);
    dst[(size_t)(rowbase + 0) * HH + h] = acc0 + bias;
    dst[(size_t)(rowbase + 1) * HH + h] = acc1 + bias;
    dst[(size_t)(rowbase + 2) * HH + h] = acc2 + bias;
    dst[(size_t)(rowbase + 3) * HH + h] = acc3 + bias;
}

// ---------------------------------------------------------------------------
// Scoring v2: 64q x 32k tile per 256-thread block; each thread owns a 4q x 2k
// register block (8 tanh / 8 FMA / 7 LDS per h-iter -> MUFU saturating).
// hks padded to stride 33: bk addr bank = (2*lane*33 + h) mod 32 = 2*lane+h,
// all distinct for lanes 0..15 -> conflict-free. hqs reads are 2-address
// broadcasts (no pad needed -> float4 prologue fill).
// ---------------------------------------------------------------------------
__global__ __launch_bounds__(256) void score_kernel(
    const float* __restrict__ W2, const float* __restrict__ b2,
    float* __restrict__ out)
{
    __shared__ float hqs[64][32];
    __shared__ float hks[32][33];
    __shared__ float w2s[32];

    const int b  = blockIdx.z;
    const int q0 = blockIdx.y * 64;
    const int k0 = blockIdx.x * 32;
    const int tid = threadIdx.x;

    {
        // hq tile: 64*32 floats = 512 float4
        const float4* __restrict__ hq_g =
            (const float4*)(g_hq + (size_t)(b * NQv + q0) * HH);
        float4* hqv = (float4*)&hqs[0][0];
        hqv[tid]       = hq_g[tid];
        hqv[tid + 256] = hq_g[tid + 256];
        // hk tile: 32*32 floats, scalar into padded array
        const float* __restrict__ hk_g = g_hk + (size_t)(b * NKv + k0) * HH;
        #pragma unroll
        for (int it = 0; it < 4; ++it) {
            const int i = tid + it * 256;
            hks[i >> 5][i & 31] = hk_g[i];
        }
        if (tid < 32) w2s[tid] = W2[tid];
    }
    __syncthreads();

    const int kk = (tid & 15) * 2;
    const int qq = (tid >> 4) * 4;

    float a00 = 0.f, a01 = 0.f, a10 = 0.f, a11 = 0.f;
    float a20 = 0.f, a21 = 0.f, a30 = 0.f, a31 = 0.f;

    #pragma unroll
    for (int h = 0; h < HH; ++h) {
        const float w   = w2s[h];
        const float bk0 = hks[kk][h];
        const float bk1 = hks[kk + 1][h];
        const float q0v = hqs[qq + 0][h];
        const float q1v = hqs[qq + 1][h];
        const float q2v = hqs[qq + 2][h];
        const float q3v = hqs[qq + 3][h];
        a00 = fmaf(w, tanh_fast(q0v + bk0), a00);
        a01 = fmaf(w, tanh_fast(q0v + bk1), a01);
        a10 = fmaf(w, tanh_fast(q1v + bk0), a10);
        a11 = fmaf(w, tanh_fast(q1v + bk1), a11);
        a20 = fmaf(w, tanh_fast(q2v + bk0), a20);
        a21 = fmaf(w, tanh_fast(q2v + bk1), a21);
        a30 = fmaf(w, tanh_fast(q3v + bk0), a30);
        a31 = fmaf(w, tanh_fast(q3v + bk1), a31);
    }

    const float bias = __ldg(b2);
    float* __restrict__ o =
        out + (size_t)(b * NQv + q0 + qq) * NKv + k0 + kk;
    *(float2*)(o + 0 * NKv) = make_float2(a00 + bias, a01 + bias);
    *(float2*)(o + 1 * NKv) = make_float2(a10 + bias, a11 + bias);
    *(float2*)(o + 2 * NKv) = make_float2(a20 + bias, a21 + bias);
    *(float2*)(o + 3 * NKv) = make_float2(a30 + bias, a31 + bias);
}

extern "C" void kernel_launch(void* const* d_in, const int* in_sizes, int n_in,
                              void* d_out, int out_size)
{
    const float* keys    = (const float*)d_in[0];
    const float* queries = (const float*)d_in[1];
    const float* W1      = (const float*)d_in[2];
    const float* b1      = (const float*)d_in[3];
    const float* W2      = (const float*)d_in[4];
    const float* b2      = (const float*)d_in[5];
    float* out = (float*)d_out;

    proj_kernel<<<dim3(64, 2, 1), 256>>>(keys, queries, W1, b1);
    score_kernel<<<dim3(NKv / 32, NQv / 64, BB), 256>>>(W2, b2, out);
}

// round 3
// speedup vs baseline: 1.6350x; 1.1259x over previous
#include <cuda_runtime.h>
#include <cuda_fp16.h>

#define BB 2
#define NQv 1024
#define NKv 1024
#define DD 512
#define HH 32

// Scratch (no cudaMalloc allowed). 16B-aligned for float4 loads.
// g_hk2[pair][h] = half2(hk[2p][h]+b1[h], hk[2p+1][h]+b1[h])  -- k-pairs
// g_hq2[row][h]  = half2(hq[row][h], hq[row][h])              -- duplicated
__device__ __align__(16) __half2 g_hk2[(BB * NKv / 2) * HH];
__device__ __align__(16) __half2 g_hq2[(BB * NQv) * HH];

__device__ __forceinline__ unsigned tanh2u(unsigned x) {
    unsigned y;
    asm("tanh.approx.f16x2 %0, %1;" : "=r"(y) : "r"(x));
    return y;
}

// ---------------------------------------------------------------------------
// Projection v3: block = 256 thr (8 warps) handles 16 rows of one tensor.
// Rows staged in smem via coalesced float4 LDG. Warp w owns rows 2w,2w+1;
// lane = h. W1 columns read lane-coalesced (128B/warp), L1-resident (64KB).
// Emits f16 outputs pre-packed for the score kernel.
// ---------------------------------------------------------------------------
__global__ __launch_bounds__(256) void proj_kernel(
    const float* __restrict__ keys, const float* __restrict__ queries,
    const float* __restrict__ W1, const float* __restrict__ b1)
{
    __shared__ float as[16][DD];    // 32 KB
    const int z    = blockIdx.y;
    const int tid  = threadIdx.x;
    const int h    = tid & 31;
    const int warp = tid >> 5;
    const int row0 = blockIdx.x * 16;            // tile base row (0..2047)
    const float* __restrict__ src = z ? queries : keys;

    // Stage 16 rows: 2048 float4, 8 per thread, coalesced.
    {
        const float4* __restrict__ sg = (const float4*)(src + (size_t)row0 * DD);
        float4* sv = (float4*)&as[0][0];
        #pragma unroll
        for (int i = 0; i < 8; ++i)
            sv[tid + i * 256] = __ldg(&sg[tid + i * 256]);
    }
    __syncthreads();

    const float* __restrict__ wp = W1 + (size_t)(z * DD) * HH + h;
    float acc0 = 0.f, acc1 = 0.f;

    #pragma unroll 4
    for (int d4 = 0; d4 < DD / 4; ++d4) {
        const float4 a0 = *(const float4*)&as[2 * warp + 0][d4 * 4];
        const float4 a1 = *(const float4*)&as[2 * warp + 1][d4 * 4];
        const float w0 = __ldg(wp + (d4 * 4 + 0) * HH);
        const float w1v = __ldg(wp + (d4 * 4 + 1) * HH);
        const float w2v = __ldg(wp + (d4 * 4 + 2) * HH);
        const float w3v = __ldg(wp + (d4 * 4 + 3) * HH);
        acc0 = fmaf(a0.x, w0, acc0);  acc1 = fmaf(a1.x, w0, acc1);
        acc0 = fmaf(a0.y, w1v, acc0); acc1 = fmaf(a1.y, w1v, acc1);
        acc0 = fmaf(a0.z, w2v, acc0); acc1 = fmaf(a1.z, w2v, acc1);
        acc0 = fmaf(a0.w, w3v, acc0); acc1 = fmaf(a1.w, w3v, acc1);
    }

    if (z == 0) {
        const float bias = __ldg(&b1[h]);
        // k-pair (2w, 2w+1) of tile -> pair index (row0 + 2w)/2
        const int pair = (row0 >> 1) + warp;
        g_hk2[(size_t)pair * HH + h] = __floats2half2_rn(acc0 + bias, acc1 + bias);
    } else {
        const int r = row0 + 2 * warp;
        g_hq2[(size_t)(r + 0) * HH + h] = __float2half2_rn(acc0);
        g_hq2[(size_t)(r + 1) * HH + h] = __float2half2_rn(acc1);
    }
}

// ---------------------------------------------------------------------------
// Scoring v3 (f16x2): 64q x 32k tile, 256 thr. Thread owns 4q x 1 k-pair.
// Per h-iter: 4 HADD2 + 4 tanh.f16x2 (covers 8 tanh) + 8 F2F + 8 FFMA(f32).
// MUFU instruction count halved vs f32. fp32 accumulation for accuracy.
// ---------------------------------------------------------------------------
__global__ __launch_bounds__(256) void score_kernel(
    const float* __restrict__ W2, const float* __restrict__ b2,
    float* __restrict__ out)
{
    __shared__ __half2 hqs2[64][33];   // (v,v) duplicated, padded
    __shared__ __half2 hks2[16][33];   // (bk0,bk1) k-pairs, padded
    __shared__ float   w2s[32];

    const int b   = blockIdx.z;
    const int q0  = blockIdx.y * 64;
    const int k0  = blockIdx.x * 32;
    const int tid = threadIdx.x;

    {
        // hq tile: 64 rows x 32 half2 = 2048 words, 8/thread, scatter to pad
        const __half2* __restrict__ hq_g = g_hq2 + (size_t)(b * NQv + q0) * HH;
        #pragma unroll
        for (int it = 0; it < 8; ++it) {
            const int i = tid + it * 256;
            hqs2[i >> 5][i & 31] = hq_g[i];
        }
        // hk tile: 16 pairs x 32 half2 = 512 words, 2/thread
        const __half2* __restrict__ hk_g = g_hk2 + (size_t)((b * NKv + k0) >> 1) * HH;
        #pragma unroll
        for (int it = 0; it < 2; ++it) {
            const int i = tid + it * 256;
            hks2[i >> 5][i & 31] = hk_g[i];
        }
        if (tid < 32) w2s[tid] = W2[tid];
    }
    __syncthreads();

    const int kp = tid & 15;           // k-pair within tile
    const int qq = (tid >> 4) * 4;     // q base within tile

    float a00 = 0.f, a01 = 0.f, a10 = 0.f, a11 = 0.f;
    float a20 = 0.f, a21 = 0.f, a30 = 0.f, a31 = 0.f;

    #pragma unroll
    for (int h = 0; h < HH; ++h) {
        const float   w   = w2s[h];
        const __half2 bk2 = hks2[kp][h];
        const __half2 x0  = __hadd2(hqs2[qq + 0][h], bk2);
        const __half2 x1  = __hadd2(hqs2[qq + 1][h], bk2);
        const __half2 x2  = __hadd2(hqs2[qq + 2][h], bk2);
        const __half2 x3  = __hadd2(hqs2[qq + 3][h], bk2);
        __half2 t0, t1, t2, t3;
        *(unsigned*)&t0 = tanh2u(*(const unsigned*)&x0);
        *(unsigned*)&t1 = tanh2u(*(const unsigned*)&x1);
        *(unsigned*)&t2 = tanh2u(*(const unsigned*)&x2);
        *(unsigned*)&t3 = tanh2u(*(const unsigned*)&x3);
        a00 = fmaf(w, __low2float(t0), a00); a01 = fmaf(w, __high2float(t0), a01);
        a10 = fmaf(w, __low2float(t1), a10); a11 = fmaf(w, __high2float(t1), a11);
        a20 = fmaf(w, __low2float(t2), a20); a21 = fmaf(w, __high2float(t2), a21);
        a30 = fmaf(w, __low2float(t3), a30); a31 = fmaf(w, __high2float(t3), a31);
    }

    const float bias = __ldg(b2);
    float* __restrict__ o =
        out + (size_t)(b * NQv + q0 + qq) * NKv + k0 + 2 * kp;
    *(float2*)(o + 0 * NKv) = make_float2(a00 + bias, a01 + bias);
    *(float2*)(o + 1 * NKv) = make_float2(a10 + bias, a11 + bias);
    *(float2*)(o + 2 * NKv) = make_float2(a20 + bias, a21 + bias);
    *(float2*)(o + 3 * NKv) = make_float2(a30 + bias, a31 + bias);
}

extern "C" void kernel_launch(void* const* d_in, const int* in_sizes, int n_in,
                              void* d_out, int out_size)
{
    const float* keys    = (const float*)d_in[0];
    const float* queries = (const float*)d_in[1];
    const float* W1      = (const float*)d_in[2];
    const float* b1      = (const float*)d_in[3];
    const float* W2      = (const float*)d_in[4];
    const float* b2      = (const float*)d_in[5];
    float* out = (float*)d_out;

    // 128 row-tiles per tensor (16 rows each), y = tensor select
    proj_kernel<<<dim3(128, 2, 1), 256>>>(keys, queries, W1, b1);
    score_kernel<<<dim3(NKv / 32, NQv / 64, BB), 256>>>(W2, b2, out);
}

// round 4
// speedup vs baseline: 1.8570x; 1.1358x over previous
#include <cuda_runtime.h>
#include <cuda_fp16.h>

#define BB 2
#define NQv 1024
#define NKv 1024
#define DD 512
#define HH 32

// Scratch (no cudaMalloc allowed). 16B-aligned for vector loads.
// g_hk2[pair][h] = half2(hk[2p][h]+b1[h], hk[2p+1][h]+b1[h])  -- k-pairs
// g_hq2[row][h]  = half2(hq[row][h], hq[row][h])              -- duplicated
__device__ __align__(16) __half2 g_hk2[(BB * NKv / 2) * HH];
__device__ __align__(16) __half2 g_hq2[(BB * NQv) * HH];

__device__ __forceinline__ unsigned tanh2u(unsigned x) {
    unsigned y;
    asm("tanh.approx.f16x2 %0, %1;" : "=r"(y) : "r"(x));
    return y;
}

// ---------------------------------------------------------------------------
// Projection v4: C[2048,32] = A[2048,512] @ W[512,32] per tensor.
// Block = 256 thr handles 32 rows; K split into 4 chunks of 128.
// Both operands staged in smem (A 16KB + W 16KB). Thread owns 4 rows x 1 h.
// Inner: 4 broadcast LDS.128 (A) + 4 conflict-free LDS.32 (W) + 16 FMA
// -> FMA-pipe bound. Grid 128 blocks ~ one wave.
// ---------------------------------------------------------------------------
__global__ __launch_bounds__(256) void proj_kernel(
    const float* __restrict__ keys, const float* __restrict__ queries,
    const float* __restrict__ W1, const float* __restrict__ b1)
{
    __shared__ float as[32][128];   // A chunk: 32 rows x 128 d  (16 KB)
    __shared__ float ws[128][32];   // W chunk: 128 d x 32 h     (16 KB)

    const int z    = blockIdx.y;
    const int tid  = threadIdx.x;
    const int h    = tid & 31;
    const int warp = tid >> 5;
    const int row0 = blockIdx.x * 32;
    const float* __restrict__ src = z ? queries : keys;

    float acc0 = 0.f, acc1 = 0.f, acc2 = 0.f, acc3 = 0.f;

    for (int c = 0; c < 4; ++c) {
        // Stage A chunk: rows row0..row0+31, cols c*128..c*128+127.
        // 1024 float4, 4/thread, coalesced within each 32-float4 row segment.
        {
            const float4* __restrict__ ag =
                (const float4*)(src + (size_t)row0 * DD + c * 128);
            float4* av = (float4*)&as[0][0];
            #pragma unroll
            for (int i = 0; i < 4; ++i) {
                const int idx = tid + i * 256;       // = r*32 + j
                const int r = idx >> 5, j = idx & 31;
                av[idx] = __ldg(&ag[(size_t)r * (DD / 4) + j]);
            }
        }
        // Stage W chunk: rows z*512 + c*128 .. +127, all 32 h. 1024 float4.
        {
            const float4* __restrict__ wg =
                (const float4*)(W1 + (size_t)(z * DD + c * 128) * HH);
            float4* wv = (float4*)&ws[0][0];
            #pragma unroll
            for (int i = 0; i < 4; ++i)
                wv[tid + i * 256] = __ldg(&wg[tid + i * 256]);
        }
        __syncthreads();

        #pragma unroll 8
        for (int d4 = 0; d4 < 32; ++d4) {
            const float4 a0 = *(const float4*)&as[4 * warp + 0][d4 * 4];
            const float4 a1 = *(const float4*)&as[4 * warp + 1][d4 * 4];
            const float4 a2 = *(const float4*)&as[4 * warp + 2][d4 * 4];
            const float4 a3 = *(const float4*)&as[4 * warp + 3][d4 * 4];
            const float w0 = ws[d4 * 4 + 0][h];
            const float w1v = ws[d4 * 4 + 1][h];
            const float w2v = ws[d4 * 4 + 2][h];
            const float w3v = ws[d4 * 4 + 3][h];
            acc0 = fmaf(a0.x, w0, acc0); acc0 = fmaf(a0.y, w1v, acc0);
            acc0 = fmaf(a0.z, w2v, acc0); acc0 = fmaf(a0.w, w3v, acc0);
            acc1 = fmaf(a1.x, w0, acc1); acc1 = fmaf(a1.y, w1v, acc1);
            acc1 = fmaf(a1.z, w2v, acc1); acc1 = fmaf(a1.w, w3v, acc1);
            acc2 = fmaf(a2.x, w0, acc2); acc2 = fmaf(a2.y, w1v, acc2);
            acc2 = fmaf(a2.z, w2v, acc2); acc2 = fmaf(a2.w, w3v, acc2);
            acc3 = fmaf(a3.x, w0, acc3); acc3 = fmaf(a3.y, w1v, acc3);
            acc3 = fmaf(a3.z, w2v, acc3); acc3 = fmaf(a3.w, w3v, acc3);
        }
        __syncthreads();
    }

    const int r0 = row0 + 4 * warp;
    if (z == 0) {
        const float bias = __ldg(&b1[h]);
        const int pair = r0 >> 1;
        g_hk2[(size_t)(pair + 0) * HH + h] = __floats2half2_rn(acc0 + bias, acc1 + bias);
        g_hk2[(size_t)(pair + 1) * HH + h] = __floats2half2_rn(acc2 + bias, acc3 + bias);
    } else {
        g_hq2[(size_t)(r0 + 0) * HH + h] = __float2half2_rn(acc0);
        g_hq2[(size_t)(r0 + 1) * HH + h] = __float2half2_rn(acc1);
        g_hq2[(size_t)(r0 + 2) * HH + h] = __float2half2_rn(acc2);
        g_hq2[(size_t)(r0 + 3) * HH + h] = __float2half2_rn(acc3);
    }
}

// ---------------------------------------------------------------------------
// Scoring v4: 64q x 32k tile, 256 thr, thread owns 4q x 1 k-pair.
// fp16 (HFMA2) accumulation in blocks of 8 h-steps, flushed to f32 master
// accumulators. XU pipe per iter: 4 tanh.f16x2 + amortized 1 F2F (vs 8-MUFU
// equivalent before) -> ~36 XU-cyc/iter vs 64.
// ---------------------------------------------------------------------------
__global__ __launch_bounds__(256) void score_kernel(
    const float* __restrict__ W2, const float* __restrict__ b2,
    float* __restrict__ out)
{
    __shared__ __half2 hqs2[64][33];   // (v,v) duplicated, padded
    __shared__ __half2 hks2[16][33];   // (bk0,bk1) k-pairs, padded
    __shared__ __half2 w2s2[32];       // (w,w)

    const int b   = blockIdx.z;
    const int q0  = blockIdx.y * 64;
    const int k0  = blockIdx.x * 32;
    const int tid = threadIdx.x;

    {
        const __half2* __restrict__ hq_g = g_hq2 + (size_t)(b * NQv + q0) * HH;
        #pragma unroll
        for (int it = 0; it < 8; ++it) {
            const int i = tid + it * 256;
            hqs2[i >> 5][i & 31] = hq_g[i];
        }
        const __half2* __restrict__ hk_g = g_hk2 + (size_t)((b * NKv + k0) >> 1) * HH;
        #pragma unroll
        for (int it = 0; it < 2; ++it) {
            const int i = tid + it * 256;
            hks2[i >> 5][i & 31] = hk_g[i];
        }
        if (tid < 32) w2s2[tid] = __float2half2_rn(__ldg(&W2[tid]));
    }
    __syncthreads();

    const int kp = tid & 15;           // k-pair within tile
    const int qq = (tid >> 4) * 4;     // q base within tile

    float a00 = 0.f, a01 = 0.f, a10 = 0.f, a11 = 0.f;
    float a20 = 0.f, a21 = 0.f, a30 = 0.f, a31 = 0.f;

    #pragma unroll
    for (int hb = 0; hb < 4; ++hb) {
        __half2 c0 = __float2half2_rn(0.f);
        __half2 c1 = c0, c2 = c0, c3 = c0;
        #pragma unroll
        for (int hi = 0; hi < 8; ++hi) {
            const int h = hb * 8 + hi;
            const __half2 w2h = w2s2[h];
            const __half2 bk2 = hks2[kp][h];
            const __half2 x0  = __hadd2(hqs2[qq + 0][h], bk2);
            const __half2 x1  = __hadd2(hqs2[qq + 1][h], bk2);
            const __half2 x2  = __hadd2(hqs2[qq + 2][h], bk2);
            const __half2 x3  = __hadd2(hqs2[qq + 3][h], bk2);
            __half2 t0, t1, t2, t3;
            *(unsigned*)&t0 = tanh2u(*(const unsigned*)&x0);
            *(unsigned*)&t1 = tanh2u(*(const unsigned*)&x1);
            *(unsigned*)&t2 = tanh2u(*(const unsigned*)&x2);
            *(unsigned*)&t3 = tanh2u(*(const unsigned*)&x3);
            c0 = __hfma2(w2h, t0, c0);
            c1 = __hfma2(w2h, t1, c1);
            c2 = __hfma2(w2h, t2, c2);
            c3 = __hfma2(w2h, t3, c3);
        }
        a00 += __low2float(c0); a01 += __high2float(c0);
        a10 += __low2float(c1); a11 += __high2float(c1);
        a20 += __low2float(c2); a21 += __high2float(c2);
        a30 += __low2float(c3); a31 += __high2float(c3);
    }

    const float bias = __ldg(b2);
    float* __restrict__ o =
        out + (size_t)(b * NQv + q0 + qq) * NKv + k0 + 2 * kp;
    *(float2*)(o + 0 * NKv) = make_float2(a00 + bias, a01 + bias);
    *(float2*)(o + 1 * NKv) = make_float2(a10 + bias, a11 + bias);
    *(float2*)(o + 2 * NKv) = make_float2(a20 + bias, a21 + bias);
    *(float2*)(o + 3 * NKv) = make_float2(a30 + bias, a31 + bias);
}

extern "C" void kernel_launch(void* const* d_in, const int* in_sizes, int n_in,
                              void* d_out, int out_size)
{
    const float* keys    = (const float*)d_in[0];
    const float* queries = (const float*)d_in[1];
    const float* W1      = (const float*)d_in[2];
    const float* b1      = (const float*)d_in[3];
    const float* W2      = (const float*)d_in[4];
    const float* b2      = (const float*)d_in[5];
    float* out = (float*)d_out;

    proj_kernel<<<dim3(64, 2, 1), 256>>>(keys, queries, W1, b1);
    score_kernel<<<dim3(NKv / 32, NQv / 64, BB), 256>>>(W2, b2, out);
}